// round 1
// baseline (speedup 1.0000x reference)
#include <cuda_runtime.h>
#include <cuda_bf16.h>
#include <math_constants.h>

// Problem constants (fixed by the dataset)
static constexpr int B_  = 4;
static constexpr int D_  = 512;
static constexpr int L_  = 4096;
static constexpr int N1_ = 1167;
static constexpr int N2_ = 8921;

// ---------------------------------------------------------------------------
// Scratch (no cudaMalloc allowed -> __device__ globals)
// ---------------------------------------------------------------------------
__device__ float g_E1[(size_t)B_ * N1_ * L_];   // E1 / A1   [B, N1, L]  ~76.5 MB
__device__ float g_C1[(size_t)B_ * N1_ * D_];   // C1        [B, N1, D]  ~9.6 MB
__device__ float g_Q2[(size_t)B_ * N2_ * D_];   // Q2 (modulated) [B, N2, D] ~73 MB

// ---------------------------------------------------------------------------
// Tiled SGEMM: C[b] = A[b] (MxK, k-contig) * B[b]
//   TB=false: B is [K x N], n-contig (NN)
//   TB=true : B is [N x K], k-contig (NT, i.e. C = A * B^T)
//   EMUL    : epilogue C[m,n] *= E[m*N + n] (E unbatched)
// Tile: 128x128x8, 256 threads, 8x8 per-thread microtile.
// ---------------------------------------------------------------------------
#define BM 128
#define BN 128
#define BK 8
#define TM 8
#define TN 8

template <bool TB, bool EMUL>
__global__ void __launch_bounds__(256)
sgemm_kernel(const float* __restrict__ A, const float* __restrict__ Bm,
             float* __restrict__ C, const float* __restrict__ E,
             int M, int N, int K,
             long long sA, long long sB, long long sC)
{
    __shared__ float As[BK][BM];
    __shared__ float Bs[BK][BN];

    const int bz = blockIdx.z;
    A  += (long long)bz * sA;
    Bm += (long long)bz * sB;
    C  += (long long)bz * sC;

    const int m0 = blockIdx.y * BM;
    const int n0 = blockIdx.x * BN;

    const int tid = threadIdx.x;
    const int tx  = tid & 15;       // 0..15
    const int ty  = tid >> 4;       // 0..15
    const int tm  = ty * TM;        // row within tile
    const int tn  = tx * TN;        // col within tile

    // A-tile load mapping: [BM x BK] (k-contig), 4 floats per thread
    const int a_row  = tid >> 1;          // 0..127
    const int a_col4 = (tid & 1) * 4;     // 0 or 4
    // B-tile load mapping (NN): [BK x BN] (n-contig)
    const int bk_  = tid >> 5;            // 0..7
    const int bn4_ = (tid & 31) * 4;      // 0..124

    const bool kAligned = ((K & 3) == 0);

    float acc[TM][TN];
#pragma unroll
    for (int i = 0; i < TM; i++)
#pragma unroll
        for (int j = 0; j < TN; j++) acc[i][j] = 0.0f;

    for (int kt = 0; kt < K; kt += BK) {
        // ---- load A tile (transpose-store into As[k][m]) ----
        {
            const int gm = m0 + a_row;
            const int gk = kt + a_col4;
            float4 v = make_float4(0.f, 0.f, 0.f, 0.f);
            if (gm < M) {
                const float* src = A + (long long)gm * K + gk;
                if (kAligned && gk + 3 < K) {
                    v = *reinterpret_cast<const float4*>(src);
                } else {
                    float* p = reinterpret_cast<float*>(&v);
#pragma unroll
                    for (int j = 0; j < 4; j++)
                        if (gk + j < K) p[j] = src[j];
                }
            }
            As[a_col4 + 0][a_row] = v.x;
            As[a_col4 + 1][a_row] = v.y;
            As[a_col4 + 2][a_row] = v.z;
            As[a_col4 + 3][a_row] = v.w;
        }
        // ---- load B tile ----
        if constexpr (TB) {
            // B is [N x K] k-contig; transpose-store into Bs[k][n]
            const int gn = n0 + a_row;
            const int gk = kt + a_col4;
            float4 v = make_float4(0.f, 0.f, 0.f, 0.f);
            if (gn < N) {
                const float* src = Bm + (long long)gn * K + gk;
                if (kAligned && gk + 3 < K) {
                    v = *reinterpret_cast<const float4*>(src);
                } else {
                    float* p = reinterpret_cast<float*>(&v);
#pragma unroll
                    for (int j = 0; j < 4; j++)
                        if (gk + j < K) p[j] = src[j];
                }
            }
            Bs[a_col4 + 0][a_row] = v.x;
            Bs[a_col4 + 1][a_row] = v.y;
            Bs[a_col4 + 2][a_row] = v.z;
            Bs[a_col4 + 3][a_row] = v.w;
        } else {
            // B is [K x N] n-contig; direct store into Bs[k][n]
            const int gk = kt + bk_;
            const int gn = n0 + bn4_;
            float4 v = make_float4(0.f, 0.f, 0.f, 0.f);
            if (gk < K) {
                const float* src = Bm + (long long)gk * N + gn;
                if (gn + 3 < N) {
                    v = *reinterpret_cast<const float4*>(src);
                } else {
                    float* p = reinterpret_cast<float*>(&v);
#pragma unroll
                    for (int j = 0; j < 4; j++)
                        if (gn + j < N) p[j] = src[j];
                }
            }
            *reinterpret_cast<float4*>(&Bs[bk_][bn4_]) = v;
        }
        __syncthreads();

        // ---- compute ----
#pragma unroll
        for (int k = 0; k < BK; k++) {
            float ar[TM], br[TN];
#pragma unroll
            for (int i = 0; i < TM; i += 4)
                *reinterpret_cast<float4*>(&ar[i]) =
                    *reinterpret_cast<const float4*>(&As[k][tm + i]);
#pragma unroll
            for (int j = 0; j < TN; j += 4)
                *reinterpret_cast<float4*>(&br[j]) =
                    *reinterpret_cast<const float4*>(&Bs[k][tn + j]);
#pragma unroll
            for (int i = 0; i < TM; i++)
#pragma unroll
                for (int j = 0; j < TN; j++)
                    acc[i][j] = fmaf(ar[i], br[j], acc[i][j]);
        }
        __syncthreads();
    }

    // ---- store (N is always a multiple of 4 here: D=512 or L=4096) ----
#pragma unroll
    for (int i = 0; i < TM; i++) {
        const int gm = m0 + tm + i;
        if (gm >= M) continue;
#pragma unroll
        for (int j = 0; j < TN; j += 4) {
            const int gn = n0 + tn + j;
            if (gn + 3 < N) {
                float4 v = make_float4(acc[i][j], acc[i][j + 1],
                                       acc[i][j + 2], acc[i][j + 3]);
                if constexpr (EMUL) {
                    const float* e = E + (long long)gm * N + gn;
                    v.x *= e[0]; v.y *= e[1]; v.z *= e[2]; v.w *= e[3];
                }
                *reinterpret_cast<float4*>(C + (long long)gm * N + gn) = v;
            } else {
#pragma unroll
                for (int jj = 0; jj < 4; jj++) {
                    const int g = gn + jj;
                    if (g < N) {
                        float v = acc[i][j + jj];
                        if constexpr (EMUL) v *= E[(long long)gm * N + g];
                        C[(long long)gm * N + g] = v;
                    }
                }
            }
        }
    }
}

// ---------------------------------------------------------------------------
// Row softmax (in place). One block per row, rowlen % 4 == 0.
// ---------------------------------------------------------------------------
__global__ void __launch_bounds__(256)
softmax_rows(float* __restrict__ X, int rowlen)
{
    const long long row = blockIdx.x;
    float* x = X + row * (long long)rowlen;
    float4* x4 = reinterpret_cast<float4*>(x);
    const int n4 = rowlen >> 2;
    const int tid = threadIdx.x;
    const int T = blockDim.x;
    __shared__ float sred[32];

    // pass 1: max
    float m = -CUDART_INF_F;
    for (int i = tid; i < n4; i += T) {
        float4 v = x4[i];
        m = fmaxf(m, fmaxf(fmaxf(v.x, v.y), fmaxf(v.z, v.w)));
    }
#pragma unroll
    for (int o = 16; o; o >>= 1) m = fmaxf(m, __shfl_xor_sync(0xffffffffu, m, o));
    if ((tid & 31) == 0) sred[tid >> 5] = m;
    __syncthreads();
    if (tid < 32) {
        float v = (tid < (T >> 5)) ? sred[tid] : -CUDART_INF_F;
#pragma unroll
        for (int o = 16; o; o >>= 1) v = fmaxf(v, __shfl_xor_sync(0xffffffffu, v, o));
        if (tid == 0) sred[0] = v;
    }
    __syncthreads();
    m = sred[0];
    __syncthreads();

    // pass 2: exp + sum
    float s = 0.0f;
    for (int i = tid; i < n4; i += T) {
        float4 v = x4[i];
        v.x = __expf(v.x - m); v.y = __expf(v.y - m);
        v.z = __expf(v.z - m); v.w = __expf(v.w - m);
        x4[i] = v;
        s += v.x + v.y + v.z + v.w;
    }
#pragma unroll
    for (int o = 16; o; o >>= 1) s += __shfl_xor_sync(0xffffffffu, s, o);
    if ((tid & 31) == 0) sred[tid >> 5] = s;
    __syncthreads();
    if (tid < 32) {
        float v = (tid < (T >> 5)) ? sred[tid] : 0.0f;
#pragma unroll
        for (int o = 16; o; o >>= 1) v += __shfl_xor_sync(0xffffffffu, v, o);
        if (tid == 0) sred[0] = v;
    }
    __syncthreads();
    const float inv = 1.0f / sred[0];

    // pass 3: normalize
    for (int i = tid; i < n4; i += T) {
        float4 v = x4[i];
        v.x *= inv; v.y *= inv; v.z *= inv; v.w *= inv;
        x4[i] = v;
    }
}

// ---------------------------------------------------------------------------
// Launch: 7-stage pipeline on the default stream (graph-capturable).
// Output layout: C2 [B, N2, D] fp32, then A2 [B, N2, L] fp32.
// ---------------------------------------------------------------------------
extern "C" void kernel_launch(void* const* d_in, const int* in_sizes, int n_in,
                              void* d_out, int out_size)
{
    const float* H   = (const float*)d_in[0];   // [B, D, L]
    const float* Q1w = (const float*)d_in[1];   // [N1, D]
    const float* Q2w = (const float*)d_in[2];   // [N2, D]
    const float* Q12 = (const float*)d_in[3];   // [N2, N1]

    float* C2 = (float*)d_out;                                  // [B, N2, D]
    float* A2 = (float*)d_out + (long long)B_ * N2_ * D_;       // [B, N2, L]

    float *pE1, *pC1, *pQ2;
    cudaGetSymbolAddress((void**)&pE1, g_E1);
    cudaGetSymbolAddress((void**)&pC1, g_C1);
    cudaGetSymbolAddress((void**)&pQ2, g_Q2);

    const long long sH  = (long long)D_ * L_;
    const long long sE1 = (long long)N1_ * L_;
    const long long sC1 = (long long)N1_ * D_;
    const long long sQ2 = (long long)N2_ * D_;
    const long long sA2 = (long long)N2_ * L_;
    const long long sC2 = (long long)N2_ * D_;

    const int gy1 = (N1_ + BM - 1) / BM;   // 10
    const int gy2 = (N2_ + BM - 1) / BM;   // 70

    // 1) E1[b,n,l] = sum_d Q1w[n,d] * H[b,d,l]        (NN)
    sgemm_kernel<false, false><<<dim3(L_ / BN, gy1, B_), 256>>>(
        Q1w, H, pE1, nullptr, N1_, L_, D_, 0, sH, sE1);

    // 2) A1 = softmax_l(E1)
    softmax_rows<<<B_ * N1_, 256>>>(pE1, L_);

    // 3) C1[b,n,d] = sum_l A1[b,n,l] * H[b,d,l]       (NT)
    sgemm_kernel<true, false><<<dim3(D_ / BN, gy1, B_), 256>>>(
        pE1, H, pC1, nullptr, N1_, D_, L_, sE1, sH, sC1);

    // 4) Q2[b,m,d] = Q2w[m,d] * sum_n Q12[m,n] * C1[b,n,d]   (NN + emul)
    sgemm_kernel<false, true><<<dim3(D_ / BN, gy2, B_), 256>>>(
        Q12, pC1, pQ2, Q2w, N2_, D_, N1_, 0, sC1, sQ2);

    // 5) E2[b,m,l] = sum_d Q2[b,m,d] * H[b,d,l]       (NN) -> A2 region
    sgemm_kernel<false, false><<<dim3(L_ / BN, gy2, B_), 256>>>(
        pQ2, H, A2, nullptr, N2_, L_, D_, sQ2, sH, sA2);

    // 6) A2 = softmax_l(E2), in place
    softmax_rows<<<B_ * N2_, 256>>>(A2, L_);

    // 7) C2[b,m,d] = sum_l A2[b,m,l] * H[b,d,l]       (NT)
    sgemm_kernel<true, false><<<dim3(D_ / BN, gy2, B_), 256>>>(
        A2, H, C2, nullptr, N2_, D_, L_, sA2, sH, sC2);
}

// round 3
// speedup vs baseline: 2.1552x; 2.1552x over previous
#include <cuda_runtime.h>
#include <cstdint>
#include <math_constants.h>

// Problem constants (fixed by the dataset)
static constexpr int B_  = 4;
static constexpr int D_  = 512;
static constexpr int L_  = 4096;
static constexpr int N1_ = 1167;
static constexpr int N2_ = 8921;

// ---------------------------------------------------------------------------
// Scratch (__device__ globals; no cudaMalloc allowed)
// ---------------------------------------------------------------------------
__device__ float g_E1[(size_t)B_ * N1_ * L_];   // E1 / A1  [B, N1, L]
__device__ float g_C1[(size_t)B_ * N1_ * D_];   // C1       [B, N1, D]
__device__ float g_Q2[(size_t)B_ * N2_ * D_];   // mod. Q2  [B, N2, D]

// ---------------------------------------------------------------------------
// Helpers
// ---------------------------------------------------------------------------
__device__ __forceinline__ float tf32r(float x) {
    uint32_t o;
    asm("cvt.rna.tf32.f32 %0, %1;" : "=r"(o) : "f"(x));
    return __uint_as_float(o);
}

__device__ __forceinline__ void mma_tf32(float* c, const uint32_t* a, const uint32_t* b) {
    asm volatile(
        "mma.sync.aligned.m16n8k8.row.col.f32.tf32.tf32.f32 "
        "{%0,%1,%2,%3}, {%4,%5,%6,%7}, {%8,%9}, {%0,%1,%2,%3};"
        : "+f"(c[0]), "+f"(c[1]), "+f"(c[2]), "+f"(c[3])
        : "r"(a[0]), "r"(a[1]), "r"(a[2]), "r"(a[3]), "r"(b[0]), "r"(b[1]));
}

// ---------------------------------------------------------------------------
// tf32 warp-MMA GEMM:  C[b](MxN) = A[b](MxK, k-contig) * B[b]
//   BT=false (NN): B stored [K x N], n-contig
//   BT=true  (NT): B stored [N x K], k-contig   (C = A * B^T)
//   KA : K % 32 == 0 and all rows 16B-aligned -> float4 loads, no k guards
//   EMUL: C[m,n] *= E[m*N + n] (E unbatched)
// CTA tile 128(M) x 128(N) x 32(K); 8 warps in 4(m) x 2(n); warp tile 32x64.
// All GEMM operands are rounded to tf32 (rna) at SMEM-fill time.
// ---------------------------------------------------------------------------
#define BM 128
#define BN 128
#define BK 32

template <bool BT, bool KA, bool EMUL>
__global__ void __launch_bounds__(256, 1)
mma_gemm(const float* __restrict__ A, const float* __restrict__ Bm,
         float* __restrict__ C, const float* __restrict__ E,
         int M, int N, int K,
         long long sA, long long sB, long long sC)
{
    // A always stored [m][k], stride 36 (36 mod 32 == 4 -> conflict-free frags)
    __shared__ float As[BM][36];
    // B: NN -> [k][n] stride 136 (== 8 mod 32); NT -> [n][k] stride 36
    __shared__ float Bs[BT ? BN : BK][BT ? 36 : 136];

    const int bz = blockIdx.z;
    A  += (long long)bz * sA;
    Bm += (long long)bz * sB;
    C  += (long long)bz * sC;

    const int m0 = blockIdx.y * BM;
    const int n0 = blockIdx.x * BN;

    const int tid = threadIdx.x;
    const int wid = tid >> 5;
    const int lid = tid & 31;
    const int g   = lid >> 2;     // group id (0..7)
    const int tig = lid & 3;      // thread in group (0..3)

    const int mb = (wid & 3) * 32;   // warp m-offset within CTA tile
    const int nb = (wid >> 2) * 64;  // warp n-offset within CTA tile

    float acc[2][8][4];
#pragma unroll
    for (int mt = 0; mt < 2; mt++)
#pragma unroll
        for (int nt = 0; nt < 8; nt++)
#pragma unroll
            for (int r = 0; r < 4; r++) acc[mt][nt][r] = 0.0f;

    const int nK = (K + BK - 1) / BK;

    // ---- global-load lambdas (round to tf32 at load) ----
    auto loadA = [&](int kt, float4* aR) {
#pragma unroll
        for (int i = 0; i < 4; i++) {
            const int slot = tid + i * 256;      // 1024 float4 slots
            const int row  = slot >> 3;          // 0..127
            const int c4   = slot & 7;           // 0..7
            const int gm   = m0 + row;
            const int gk   = kt * BK + c4 * 4;
            float4 v = make_float4(0.f, 0.f, 0.f, 0.f);
            if (gm < M) {
                const float* p = A + (long long)gm * K + gk;
                if (KA) {
                    v = *reinterpret_cast<const float4*>(p);
                } else {
                    float* f = reinterpret_cast<float*>(&v);
#pragma unroll
                    for (int j = 0; j < 4; j++)
                        if (gk + j < K) f[j] = p[j];
                }
            }
            v.x = tf32r(v.x); v.y = tf32r(v.y);
            v.z = tf32r(v.z); v.w = tf32r(v.w);
            aR[i] = v;
        }
    };
    auto storeA = [&](const float4* aR) {
#pragma unroll
        for (int i = 0; i < 4; i++) {
            const int slot = tid + i * 256;
            const int row  = slot >> 3;
            const int c4   = slot & 7;
            *reinterpret_cast<float4*>(&As[row][c4 * 4]) = aR[i];
        }
    };
    auto loadB = [&](int kt, float4* bR) {
#pragma unroll
        for (int i = 0; i < 4; i++) {
            const int slot = tid + i * 256;
            float4 v = make_float4(0.f, 0.f, 0.f, 0.f);
            if (BT) {
                const int nrow = slot >> 3;        // 0..127
                const int c4   = slot & 7;
                const int gn   = n0 + nrow;
                const int gk   = kt * BK + c4 * 4;
                const float* p = Bm + (long long)gn * K + gk;
                if (KA) {
                    v = *reinterpret_cast<const float4*>(p);
                } else {
                    float* f = reinterpret_cast<float*>(&v);
#pragma unroll
                    for (int j = 0; j < 4; j++)
                        if (gk + j < K) f[j] = p[j];
                }
            } else {
                const int kr = slot >> 5;          // 0..31
                const int n4 = (slot & 31) * 4;    // 0..124
                const int gk = kt * BK + kr;
                if (KA || gk < K)
                    v = *reinterpret_cast<const float4*>(
                            Bm + (long long)gk * N + n0 + n4);
            }
            v.x = tf32r(v.x); v.y = tf32r(v.y);
            v.z = tf32r(v.z); v.w = tf32r(v.w);
            bR[i] = v;
        }
    };
    auto storeB = [&](const float4* bR) {
#pragma unroll
        for (int i = 0; i < 4; i++) {
            const int slot = tid + i * 256;
            if (BT) {
                const int nrow = slot >> 3;
                const int c4   = slot & 7;
                *reinterpret_cast<float4*>(&Bs[nrow][c4 * 4]) = bR[i];
            } else {
                const int kr = slot >> 5;
                const int n4 = (slot & 31) * 4;
                *reinterpret_cast<float4*>(&Bs[kr][n4]) = bR[i];
            }
        }
    };

    // ---- prologue ----
    {
        float4 aR[4], bR[4];
        loadA(0, aR); loadB(0, bR);
        storeA(aR);   storeB(bR);
    }
    __syncthreads();

    // ---- main loop: compute tile kt while prefetching kt+1 into registers ----
    for (int kt = 0; kt < nK; kt++) {
        float4 aN[4], bN[4];
        const bool more = (kt + 1 < nK);
        if (more) { loadA(kt + 1, aN); loadB(kt + 1, bN); }

#pragma unroll
        for (int ks = 0; ks < 4; ks++) {
            const int kb = ks * 8;
            uint32_t af[2][4];
#pragma unroll
            for (int mt = 0; mt < 2; mt++) {
                const int m = mb + mt * 16;
                af[mt][0] = __float_as_uint(As[m + g    ][kb + tig    ]);
                af[mt][1] = __float_as_uint(As[m + g + 8][kb + tig    ]);
                af[mt][2] = __float_as_uint(As[m + g    ][kb + tig + 4]);
                af[mt][3] = __float_as_uint(As[m + g + 8][kb + tig + 4]);
            }
            uint32_t bf[8][2];
#pragma unroll
            for (int nt = 0; nt < 8; nt++) {
                const int n = nb + nt * 8 + g;
                if (BT) {
                    bf[nt][0] = __float_as_uint(Bs[n][kb + tig    ]);
                    bf[nt][1] = __float_as_uint(Bs[n][kb + tig + 4]);
                } else {
                    bf[nt][0] = __float_as_uint(Bs[kb + tig    ][n]);
                    bf[nt][1] = __float_as_uint(Bs[kb + tig + 4][n]);
                }
            }
#pragma unroll
            for (int mt = 0; mt < 2; mt++)
#pragma unroll
                for (int nt = 0; nt < 8; nt++)
                    mma_tf32(acc[mt][nt], af[mt], bf[nt]);
        }

        if (more) {
            __syncthreads();
            storeA(aN); storeB(bN);
            __syncthreads();
        }
    }

    // ---- epilogue: direct register -> GMEM stores (N % 8 == 0 always) ----
#pragma unroll
    for (int mt = 0; mt < 2; mt++) {
        const int r0 = m0 + mb + mt * 16 + g;
        const int r1 = r0 + 8;
#pragma unroll
        for (int nt = 0; nt < 8; nt++) {
            const int cb = n0 + nb + nt * 8 + 2 * tig;
            if (r0 < M) {
                float2 v = make_float2(acc[mt][nt][0], acc[mt][nt][1]);
                if (EMUL) {
                    const float* e = E + (long long)r0 * N + cb;
                    v.x *= e[0]; v.y *= e[1];
                }
                *reinterpret_cast<float2*>(C + (long long)r0 * N + cb) = v;
            }
            if (r1 < M) {
                float2 v = make_float2(acc[mt][nt][2], acc[mt][nt][3]);
                if (EMUL) {
                    const float* e = E + (long long)r1 * N + cb;
                    v.x *= e[0]; v.y *= e[1];
                }
                *reinterpret_cast<float2*>(C + (long long)r1 * N + cb) = v;
            }
        }
    }
}

// ---------------------------------------------------------------------------
// Row softmax (in place). One block per row, rowlen % 4 == 0.
// ---------------------------------------------------------------------------
__global__ void __launch_bounds__(256)
softmax_rows(float* __restrict__ X, int rowlen)
{
    const long long row = blockIdx.x;
    float* x = X + row * (long long)rowlen;
    float4* x4 = reinterpret_cast<float4*>(x);
    const int n4 = rowlen >> 2;
    const int tid = threadIdx.x;
    const int T = blockDim.x;
    __shared__ float sred[32];

    float m = -CUDART_INF_F;
    for (int i = tid; i < n4; i += T) {
        float4 v = x4[i];
        m = fmaxf(m, fmaxf(fmaxf(v.x, v.y), fmaxf(v.z, v.w)));
    }
#pragma unroll
    for (int o = 16; o; o >>= 1) m = fmaxf(m, __shfl_xor_sync(0xffffffffu, m, o));
    if ((tid & 31) == 0) sred[tid >> 5] = m;
    __syncthreads();
    if (tid < 32) {
        float v = (tid < (T >> 5)) ? sred[tid] : -CUDART_INF_F;
#pragma unroll
        for (int o = 16; o; o >>= 1) v = fmaxf(v, __shfl_xor_sync(0xffffffffu, v, o));
        if (tid == 0) sred[0] = v;
    }
    __syncthreads();
    m = sred[0];
    __syncthreads();

    float s = 0.0f;
    for (int i = tid; i < n4; i += T) {
        float4 v = x4[i];
        v.x = __expf(v.x - m); v.y = __expf(v.y - m);
        v.z = __expf(v.z - m); v.w = __expf(v.w - m);
        x4[i] = v;
        s += v.x + v.y + v.z + v.w;
    }
#pragma unroll
    for (int o = 16; o; o >>= 1) s += __shfl_xor_sync(0xffffffffu, s, o);
    if ((tid & 31) == 0) sred[tid >> 5] = s;
    __syncthreads();
    if (tid < 32) {
        float v = (tid < (T >> 5)) ? sred[tid] : 0.0f;
#pragma unroll
        for (int o = 16; o; o >>= 1) v += __shfl_xor_sync(0xffffffffu, v, o);
        if (tid == 0) sred[0] = v;
    }
    __syncthreads();
    const float inv = 1.0f / sred[0];

    for (int i = tid; i < n4; i += T) {
        float4 v = x4[i];
        v.x *= inv; v.y *= inv; v.z *= inv; v.w *= inv;
        x4[i] = v;
    }
}

// ---------------------------------------------------------------------------
// Pipeline (graph-capturable: kernel launches only)
// ---------------------------------------------------------------------------
extern "C" void kernel_launch(void* const* d_in, const int* in_sizes, int n_in,
                              void* d_out, int out_size)
{
    const float* H   = (const float*)d_in[0];   // [B, D, L]
    const float* Q1w = (const float*)d_in[1];   // [N1, D]
    const float* Q2w = (const float*)d_in[2];   // [N2, D]
    const float* Q12 = (const float*)d_in[3];   // [N2, N1]

    float* C2 = (float*)d_out;                                // [B, N2, D]
    float* A2 = (float*)d_out + (long long)B_ * N2_ * D_;     // [B, N2, L]

    float *pE1, *pC1, *pQ2;
    cudaGetSymbolAddress((void**)&pE1, g_E1);
    cudaGetSymbolAddress((void**)&pC1, g_C1);
    cudaGetSymbolAddress((void**)&pQ2, g_Q2);

    const long long sH  = (long long)D_ * L_;
    const long long sE1 = (long long)N1_ * L_;
    const long long sC1 = (long long)N1_ * D_;
    const long long sQ2 = (long long)N2_ * D_;
    const long long sA2 = (long long)N2_ * L_;
    const long long sC2 = (long long)N2_ * D_;

    const int gy1 = (N1_ + BM - 1) / BM;   // 10
    const int gy2 = (N2_ + BM - 1) / BM;   // 70

    // 1) E1[b,n,l] = sum_d Q1w[n,d] * H[b,d,l]            NN (B=H, k=d rows)
    mma_gemm<false, true, false><<<dim3(L_ / BN, gy1, B_), 256>>>(
        Q1w, H, pE1, nullptr, N1_, L_, D_, 0, sH, sE1);

    // 2) A1 = softmax_l(E1)
    softmax_rows<<<B_ * N1_, 256>>>(pE1, L_);

    // 3) C1[b,n,d] = sum_l A1[b,n,l] * H[b,d,l]           NT (B=H, [N=d][K=l])
    mma_gemm<true, true, false><<<dim3(D_ / BN, gy1, B_), 256>>>(
        pE1, H, pC1, nullptr, N1_, D_, L_, sE1, sH, sC1);

    // 4) Q2[b,m,d] = Q2w[m,d] * sum_n Q12[m,n] * C1[b,n,d]  NN (B=C1), K=1167
    mma_gemm<false, false, true><<<dim3(D_ / BN, gy2, B_), 256>>>(
        Q12, pC1, pQ2, Q2w, N2_, D_, N1_, 0, sC1, sQ2);

    // 5) E2[b,m,l] = sum_d Q2[b,m,d] * H[b,d,l]           NN (B=H) -> A2 region
    mma_gemm<false, true, false><<<dim3(L_ / BN, gy2, B_), 256>>>(
        pQ2, H, A2, nullptr, N2_, L_, D_, sQ2, sH, sA2);

    // 6) A2 = softmax_l(E2), in place
    softmax_rows<<<B_ * N2_, 256>>>(A2, L_);

    // 7) C2[b,m,d] = sum_l A2[b,m,l] * H[b,d,l]           NT (B=H)
    mma_gemm<true, true, false><<<dim3(D_ / BN, gy2, B_), 256>>>(
        A2, H, C2, nullptr, N2_, D_, L_, sA2, sH, sC2);
}

// round 4
// speedup vs baseline: 3.8638x; 1.7928x over previous
#include <cuda_runtime.h>
#include <cstdint>
#include <math_constants.h>

// Problem constants (fixed by the dataset)
static constexpr int B_  = 4;
static constexpr int D_  = 512;
static constexpr int L_  = 4096;
static constexpr int N1_ = 1167;
static constexpr int N2_ = 8921;

// ---------------------------------------------------------------------------
// Scratch (__device__ globals; no cudaMalloc allowed)
// ---------------------------------------------------------------------------
__device__ float g_E1 [(size_t)B_ * N1_ * L_];   // E1 / A1  [B, N1, L]
__device__ float g_C1 [(size_t)B_ * N1_ * D_];   // C1       [B, N1, D]
__device__ float g_Q2 [(size_t)B_ * N2_ * D_];   // mod. Q2  [B, N2, D]
__device__ float g_Hr [(size_t)B_ * D_ * L_];    // tf32-rounded H
__device__ float g_Q1r[(size_t)N1_ * D_];        // tf32-rounded Q1_w
__device__ float g_Q12r[(size_t)N2_ * N1_];      // tf32-rounded Q12_w

// ---------------------------------------------------------------------------
// Helpers
// ---------------------------------------------------------------------------
__device__ __forceinline__ float tf32r(float x) {
    uint32_t o;
    asm("cvt.rna.tf32.f32 %0, %1;" : "=r"(o) : "f"(x));
    return __uint_as_float(o);
}
__device__ __forceinline__ uint32_t smem_u32(const void* p) {
    uint32_t a;
    asm("{ .reg .u64 t; cvta.to.shared.u64 t, %1; cvt.u32.u64 %0, t; }"
        : "=r"(a) : "l"(p));
    return a;
}
__device__ __forceinline__ void cp16(uint32_t dst, const float* src, int sz) {
    asm volatile("cp.async.cg.shared.global [%0], [%1], 16, %2;"
                 :: "r"(dst), "l"(src), "r"(sz));
}
__device__ __forceinline__ void cp4(uint32_t dst, const float* src, int sz) {
    asm volatile("cp.async.ca.shared.global [%0], [%1], 4, %2;"
                 :: "r"(dst), "l"(src), "r"(sz));
}
__device__ __forceinline__ void cp_commit() {
    asm volatile("cp.async.commit_group;" ::: "memory");
}
template <int N>
__device__ __forceinline__ void cp_wait() {
    asm volatile("cp.async.wait_group %0;" :: "n"(N) : "memory");
}
__device__ __forceinline__ void mma_tf32(float* c, const uint32_t* a, const uint32_t* b) {
    asm volatile(
        "mma.sync.aligned.m16n8k8.row.col.f32.tf32.tf32.f32 "
        "{%0,%1,%2,%3}, {%4,%5,%6,%7}, {%8,%9}, {%0,%1,%2,%3};"
        : "+f"(c[0]), "+f"(c[1]), "+f"(c[2]), "+f"(c[3])
        : "r"(a[0]), "r"(a[1]), "r"(a[2]), "r"(a[3]), "r"(b[0]), "r"(b[1]));
}

// ---------------------------------------------------------------------------
// tf32 warp-MMA GEMM with 3-stage cp.async pipeline.
//   C[b](MxN) = A[b](MxK, k-contig) * B[b]
//   BT=false (NN): B stored [K x N], n-contig
//   BT=true  (NT): B stored [N x K], k-contig   (C = A * B^T)
//   KA  : K % 32 == 0 and rows 16B-aligned (vector path; else 4B path for A)
//   EMUL: epilogue C[m,n] *= E[m*N + n]
//   ROUND: round epilogue output to tf32 (rna)
//   FRA : round A fragments (rna) at SMEM->register load (for unrounded A)
// CTA tile 128x128x32; 8 warps 4(m)x2(n); warp tile 32x64; 2 CTAs/SM.
// ---------------------------------------------------------------------------
#define BM 128
#define BN 128
#define BK 32
#define NSTG 3

template <bool BT, bool KA, bool EMUL, bool ROUND, bool FRA>
__global__ void __launch_bounds__(256, 2)
mma_gemm(const float* __restrict__ A, const float* __restrict__ Bm,
         float* __restrict__ C, const float* __restrict__ E,
         int M, int N, int K,
         long long sA, long long sB, long long sC)
{
    // A tile: [128][36] floats (stride 144B). B: NT [128][36]; NN [32][136] (544B).
    constexpr int A_BYTES = BM * 36 * 4;                       // 18432
    constexpr int BSTRIDE = BT ? 36 : 136;
    constexpr int B_ROWS  = BT ? BN : BK;
    constexpr int B_BYTES = B_ROWS * BSTRIDE * 4;              // 18432 / 17408

    extern __shared__ char smc[];
    const uint32_t smA = smem_u32(smc);
    const uint32_t smB = smA + NSTG * A_BYTES;

    const int bz = blockIdx.z;
    A  += (long long)bz * sA;
    Bm += (long long)bz * sB;
    C  += (long long)bz * sC;

    const int m0 = blockIdx.y * BM;
    const int n0 = blockIdx.x * BN;

    const int tid = threadIdx.x;
    const int wid = tid >> 5;
    const int lid = tid & 31;
    const int g   = lid >> 2;
    const int tig = lid & 3;
    const int mb  = (wid & 3) * 32;
    const int nb  = (wid >> 2) * 64;

    const int nK = (K + BK - 1) / BK;

    // ---- async tile issue ----
    auto issueA = [&](int kt, int buf) {
        const uint32_t base = smA + buf * A_BYTES;
        if (KA) {
#pragma unroll
            for (int i = 0; i < 4; i++) {
                const int slot = tid + i * 256;
                const int row  = slot >> 3;
                const int c4   = slot & 7;
                int gm = m0 + row; if (gm > M - 1) gm = M - 1;  // clamp (garbage rows OK)
                cp16(base + row * 144 + c4 * 16,
                     A + (long long)gm * K + kt * BK + c4 * 4, 16);
            }
        } else {
#pragma unroll
            for (int i = 0; i < 16; i++) {
                const int slot = tid + i * 256;       // 4096 scalar slots
                const int row  = slot >> 5;
                const int col  = slot & 31;
                const int gm   = m0 + row;
                const int gk   = kt * BK + col;
                const int sz   = (gk < K && gm < M) ? 4 : 0;
                const int cm   = gm < M ? gm : M - 1;
                const int ck   = gk < K ? gk : K - 1;
                cp4(base + row * 144 + col * 4, A + (long long)cm * K + ck, sz);
            }
        }
    };
    auto issueB = [&](int kt, int buf) {
        const uint32_t base = smB + buf * B_BYTES;
        if (BT) {
            // [n][k], N multiple of BN for all NT stages -> no guards
#pragma unroll
            for (int i = 0; i < 4; i++) {
                const int slot = tid + i * 256;
                const int nrow = slot >> 3;
                const int c4   = slot & 7;
                cp16(base + nrow * 144 + c4 * 16,
                     Bm + (long long)(n0 + nrow) * K + kt * BK + c4 * 4, 16);
            }
        } else {
            // [k][n], zero-fill k tail (wrong-k would pollute valid outputs)
#pragma unroll
            for (int i = 0; i < 4; i++) {
                const int slot = tid + i * 256;
                const int kr   = slot >> 5;
                const int n4   = (slot & 31) * 4;
                const int gk   = kt * BK + kr;
                const int sz   = (KA || gk < K) ? 16 : 0;
                const int ck   = gk < K ? gk : K - 1;
                cp16(base + kr * 544 + n4 * 4,
                     Bm + (long long)ck * N + n0 + n4, 16 ? sz : sz);
            }
        }
    };

    float acc[2][8][4];
#pragma unroll
    for (int mt = 0; mt < 2; mt++)
#pragma unroll
        for (int nt = 0; nt < 8; nt++)
#pragma unroll
            for (int r = 0; r < 4; r++) acc[mt][nt][r] = 0.0f;

    // ---- prologue: NSTG-1 stages in flight ----
#pragma unroll
    for (int s = 0; s < NSTG - 1; s++) {
        if (s < nK) { issueA(s, s); issueB(s, s); }
        cp_commit();
    }

    // ---- main loop ----
    for (int kt = 0; kt < nK; kt++) {
        cp_wait<NSTG - 2>();
        __syncthreads();

        const int nxt = kt + NSTG - 1;
        if (nxt < nK) { issueA(nxt, nxt % NSTG); issueB(nxt, nxt % NSTG); }
        cp_commit();

        const int buf = kt % NSTG;
        const float (*As)[36] =
            reinterpret_cast<const float(*)[36]>(smc + buf * A_BYTES);
        const float (*Bs)[BSTRIDE] =
            reinterpret_cast<const float(*)[BSTRIDE]>(smc + NSTG * A_BYTES + buf * B_BYTES);

#pragma unroll
        for (int ks = 0; ks < 4; ks++) {
            const int kb = ks * 8;
            uint32_t af[2][4];
#pragma unroll
            for (int mt = 0; mt < 2; mt++) {
                const int m = mb + mt * 16;
                float a0 = As[m + g    ][kb + tig    ];
                float a1 = As[m + g + 8][kb + tig    ];
                float a2 = As[m + g    ][kb + tig + 4];
                float a3 = As[m + g + 8][kb + tig + 4];
                if (FRA) { a0 = tf32r(a0); a1 = tf32r(a1); a2 = tf32r(a2); a3 = tf32r(a3); }
                af[mt][0] = __float_as_uint(a0);
                af[mt][1] = __float_as_uint(a1);
                af[mt][2] = __float_as_uint(a2);
                af[mt][3] = __float_as_uint(a3);
            }
            uint32_t bf[8][2];
#pragma unroll
            for (int nt = 0; nt < 8; nt++) {
                const int n = nb + nt * 8 + g;
                if (BT) {
                    bf[nt][0] = __float_as_uint(Bs[n][kb + tig    ]);
                    bf[nt][1] = __float_as_uint(Bs[n][kb + tig + 4]);
                } else {
                    bf[nt][0] = __float_as_uint(Bs[kb + tig    ][n]);
                    bf[nt][1] = __float_as_uint(Bs[kb + tig + 4][n]);
                }
            }
#pragma unroll
            for (int mt = 0; mt < 2; mt++)
#pragma unroll
                for (int nt = 0; nt < 8; nt++)
                    mma_tf32(acc[mt][nt], af[mt], bf[nt]);
        }
    }

    // ---- epilogue ----
#pragma unroll
    for (int mt = 0; mt < 2; mt++) {
        const int r0 = m0 + mb + mt * 16 + g;
        const int r1 = r0 + 8;
#pragma unroll
        for (int nt = 0; nt < 8; nt++) {
            const int cb = n0 + nb + nt * 8 + 2 * tig;
            if (r0 < M) {
                float2 v = make_float2(acc[mt][nt][0], acc[mt][nt][1]);
                if (EMUL) {
                    const float* e = E + (long long)r0 * N + cb;
                    v.x *= e[0]; v.y *= e[1];
                }
                if (ROUND) { v.x = tf32r(v.x); v.y = tf32r(v.y); }
                *reinterpret_cast<float2*>(C + (long long)r0 * N + cb) = v;
            }
            if (r1 < M) {
                float2 v = make_float2(acc[mt][nt][2], acc[mt][nt][3]);
                if (EMUL) {
                    const float* e = E + (long long)r1 * N + cb;
                    v.x *= e[0]; v.y *= e[1];
                }
                if (ROUND) { v.x = tf32r(v.x); v.y = tf32r(v.y); }
                *reinterpret_cast<float2*>(C + (long long)r1 * N + cb) = v;
            }
        }
    }
}

// ---------------------------------------------------------------------------
// Two-pass online row softmax (in place); R: tf32-round the normalized output.
// ---------------------------------------------------------------------------
template <bool R>
__global__ void __launch_bounds__(256)
softmax_rows(float* __restrict__ X, int rowlen)
{
    const long long row = blockIdx.x;
    float* x = X + row * (long long)rowlen;
    float4* x4 = reinterpret_cast<float4*>(x);
    const int n4 = rowlen >> 2;
    const int tid = threadIdx.x;
    const int T = blockDim.x;
    __shared__ float sm_m[8], sm_s[8];

    // pass 1: online max + sum(exp)
    float m = -CUDART_INF_F, s = 0.0f;
    for (int i = tid; i < n4; i += T) {
        float4 v = x4[i];
        float m4 = fmaxf(fmaxf(v.x, v.y), fmaxf(v.z, v.w));
        if (m4 > m) { s *= __expf(m - m4); m = m4; }
        s += __expf(v.x - m) + __expf(v.y - m) + __expf(v.z - m) + __expf(v.w - m);
    }
#pragma unroll
    for (int o = 16; o; o >>= 1) {
        float om = __shfl_xor_sync(0xffffffffu, m, o);
        float os = __shfl_xor_sync(0xffffffffu, s, o);
        float nm = fmaxf(m, om);
        s = s * __expf(m - nm) + os * __expf(om - nm);
        m = nm;
    }
    if ((tid & 31) == 0) { sm_m[tid >> 5] = m; sm_s[tid >> 5] = s; }
    __syncthreads();
    if (tid < 32) {
        const int nw = T >> 5;
        float mm = (tid < nw) ? sm_m[tid] : -CUDART_INF_F;
        float ss = (tid < nw) ? sm_s[tid] : 0.0f;
#pragma unroll
        for (int o = 4; o; o >>= 1) {
            float om = __shfl_xor_sync(0xffffffffu, mm, o);
            float os = __shfl_xor_sync(0xffffffffu, ss, o);
            float nm = fmaxf(mm, om);
            ss = ss * __expf(mm - nm) + os * __expf(om - nm);
            mm = nm;
        }
        if (tid == 0) { sm_m[0] = mm; sm_s[0] = ss; }
    }
    __syncthreads();
    m = sm_m[0];
    const float inv = 1.0f / sm_s[0];

    // pass 2: write normalized
    for (int i = tid; i < n4; i += T) {
        float4 v = x4[i];
        v.x = __expf(v.x - m) * inv; v.y = __expf(v.y - m) * inv;
        v.z = __expf(v.z - m) * inv; v.w = __expf(v.w - m) * inv;
        if (R) { v.x = tf32r(v.x); v.y = tf32r(v.y); v.z = tf32r(v.z); v.w = tf32r(v.w); }
        x4[i] = v;
    }
}

// ---------------------------------------------------------------------------
// Prep: tf32 rna rounding of raw inputs
// ---------------------------------------------------------------------------
__global__ void round_copy(const float* __restrict__ x, float* __restrict__ y, long long n)
{
    long long i = ((long long)blockIdx.x * blockDim.x + threadIdx.x) * 4;
    if (i + 3 < n) {
        float4 v = *reinterpret_cast<const float4*>(x + i);
        v.x = tf32r(v.x); v.y = tf32r(v.y); v.z = tf32r(v.z); v.w = tf32r(v.w);
        *reinterpret_cast<float4*>(y + i) = v;
    } else {
        for (long long j = i; j < n; j++) y[j] = tf32r(x[j]);
    }
}

// ---------------------------------------------------------------------------
// Pipeline (graph-capturable: kernel launches only)
// ---------------------------------------------------------------------------
extern "C" void kernel_launch(void* const* d_in, const int* in_sizes, int n_in,
                              void* d_out, int out_size)
{
    const float* H   = (const float*)d_in[0];   // [B, D, L]
    const float* Q1w = (const float*)d_in[1];   // [N1, D]
    const float* Q2w = (const float*)d_in[2];   // [N2, D]
    const float* Q12 = (const float*)d_in[3];   // [N2, N1]

    float* C2 = (float*)d_out;                                // [B, N2, D]
    float* A2 = (float*)d_out + (long long)B_ * N2_ * D_;     // [B, N2, L]

    float *pE1, *pC1, *pQ2, *pHr, *pQ1r, *pQ12r;
    cudaGetSymbolAddress((void**)&pE1,  g_E1);
    cudaGetSymbolAddress((void**)&pC1,  g_C1);
    cudaGetSymbolAddress((void**)&pQ2,  g_Q2);
    cudaGetSymbolAddress((void**)&pHr,  g_Hr);
    cudaGetSymbolAddress((void**)&pQ1r, g_Q1r);
    cudaGetSymbolAddress((void**)&pQ12r, g_Q12r);

    constexpr int SM_NT = NSTG * (BM * 36 * 4) + NSTG * (BN * 36 * 4);   // 110592
    constexpr int SM_NN = NSTG * (BM * 36 * 4) + NSTG * (BK * 136 * 4); // 107520

    cudaFuncSetAttribute(mma_gemm<false, true,  false, false, false>,
                         cudaFuncAttributeMaxDynamicSharedMemorySize, SM_NN);
    cudaFuncSetAttribute(mma_gemm<true,  true,  false, true,  false>,
                         cudaFuncAttributeMaxDynamicSharedMemorySize, SM_NT);
    cudaFuncSetAttribute(mma_gemm<false, false, true,  true,  false>,
                         cudaFuncAttributeMaxDynamicSharedMemorySize, SM_NN);
    cudaFuncSetAttribute(mma_gemm<true,  true,  false, false, true >,
                         cudaFuncAttributeMaxDynamicSharedMemorySize, SM_NT);

    const long long sH  = (long long)D_ * L_;
    const long long sE1 = (long long)N1_ * L_;
    const long long sC1 = (long long)N1_ * D_;
    const long long sQ2 = (long long)N2_ * D_;
    const long long sA2 = (long long)N2_ * L_;
    const long long sC2 = (long long)N2_ * D_;

    // prep: tf32-round H, Q1_w, Q12_w
    {
        long long nh = (long long)B_ * D_ * L_;
        round_copy<<<(unsigned)((nh / 4 + 255) / 256), 256>>>(H, pHr, nh);
        long long n1 = (long long)N1_ * D_;
        round_copy<<<(unsigned)((n1 / 4 + 255) / 256), 256>>>(Q1w, pQ1r, n1);
        long long n12 = (long long)N2_ * N1_;
        round_copy<<<(unsigned)((n12 / 4 + 255) / 256), 256>>>(Q12, pQ12r, n12);
    }

    const int gy1 = (N1_ + BM - 1) / BM;   // 10
    const int gy2 = (N2_ + BM - 1) / BM;   // 70

    // 1) E1 = Q1r . Hr                    NN
    mma_gemm<false, true, false, false, false>
        <<<dim3(L_ / BN, gy1, B_), 256, SM_NN>>>(
        pQ1r, pHr, pE1, nullptr, N1_, L_, D_, 0, sH, sE1);

    // 2) A1 = softmax(E1), tf32-rounded
    softmax_rows<true><<<B_ * N1_, 256>>>(pE1, L_);

    // 3) C1 = A1 . Hr^T                   NT, output tf32-rounded
    mma_gemm<true, true, false, true, false>
        <<<dim3(D_ / BN, gy1, B_), 256, SM_NT>>>(
        pE1, pHr, pC1, nullptr, N1_, D_, L_, sE1, sH, sC1);

    // 4) Q2 = (Q12r . C1) * Q2w           NN, K=1167 (4B async path), rounded
    mma_gemm<false, false, true, true, false>
        <<<dim3(D_ / BN, gy2, B_), 256, SM_NN>>>(
        pQ12r, pC1, pQ2, Q2w, N2_, D_, N1_, 0, sC1, sQ2);

    // 5) E2 = Q2 . Hr                     NN -> A2 region
    mma_gemm<false, true, false, false, false>
        <<<dim3(L_ / BN, gy2, B_), 256, SM_NN>>>(
        pQ2, pHr, A2, nullptr, N2_, L_, D_, sQ2, sH, sA2);

    // 6) A2 = softmax(E2), fp32 (output)
    softmax_rows<false><<<B_ * N2_, 256>>>(A2, L_);

    // 7) C2 = A2 . Hr^T                   NT, A fragments tf32-rounded on load
    mma_gemm<true, true, false, false, true>
        <<<dim3(D_ / BN, gy2, B_), 256, SM_NT>>>(
        A2, pHr, C2, nullptr, N2_, D_, L_, sA2, sH, sC2);
}

// round 5
// speedup vs baseline: 4.0054x; 1.0366x over previous
#include <cuda_runtime.h>
#include <cstdint>
#include <math_constants.h>

// Problem constants (fixed by the dataset)
static constexpr int B_  = 4;
static constexpr int D_  = 512;
static constexpr int L_  = 4096;
static constexpr int N1_ = 1167;
static constexpr int N2_ = 8921;

// ---------------------------------------------------------------------------
// Scratch (__device__ globals; no cudaMalloc allowed)
// ---------------------------------------------------------------------------
__device__ float g_E1 [(size_t)B_ * N1_ * L_];   // E1 / A1  [B, N1, L]
__device__ float g_C1 [(size_t)B_ * N1_ * D_];   // C1       [B, N1, D]
__device__ float g_Q2 [(size_t)B_ * N2_ * D_];   // mod. Q2  [B, N2, D]
__device__ float g_Hr [(size_t)B_ * D_ * L_];    // tf32-rounded H
__device__ float g_Q1r[(size_t)N1_ * D_];        // tf32-rounded Q1_w
__device__ float g_Q12r[(size_t)N2_ * N1_];      // tf32-rounded Q12_w

// ---------------------------------------------------------------------------
// Helpers
// ---------------------------------------------------------------------------
__device__ __forceinline__ float tf32r(float x) {
    uint32_t o;
    asm("cvt.rna.tf32.f32 %0, %1;" : "=r"(o) : "f"(x));
    return __uint_as_float(o);
}
__device__ __forceinline__ uint32_t smem_u32(const void* p) {
    uint32_t a;
    asm("{ .reg .u64 t; cvta.to.shared.u64 t, %1; cvt.u32.u64 %0, t; }"
        : "=r"(a) : "l"(p));
    return a;
}
__device__ __forceinline__ void cp16(uint32_t dst, const float* src) {
    asm volatile("cp.async.cg.shared.global [%0], [%1], 16;"
                 :: "r"(dst), "l"(src));
}
__device__ __forceinline__ void cp16z(uint32_t dst, const float* src, int sz) {
    asm volatile("cp.async.cg.shared.global [%0], [%1], 16, %2;"
                 :: "r"(dst), "l"(src), "r"(sz));
}
__device__ __forceinline__ void cp4(uint32_t dst, const float* src, int sz) {
    asm volatile("cp.async.ca.shared.global [%0], [%1], 4, %2;"
                 :: "r"(dst), "l"(src), "r"(sz));
}
__device__ __forceinline__ void cp_commit() {
    asm volatile("cp.async.commit_group;" ::: "memory");
}
template <int N>
__device__ __forceinline__ void cp_wait() {
    asm volatile("cp.async.wait_group %0;" :: "n"(N) : "memory");
}
__device__ __forceinline__ void mma_tf32(float* c, const uint32_t* a, const uint32_t* b) {
    asm volatile(
        "mma.sync.aligned.m16n8k8.row.col.f32.tf32.tf32.f32 "
        "{%0,%1,%2,%3}, {%4,%5,%6,%7}, {%8,%9}, {%0,%1,%2,%3};"
        : "+f"(c[0]), "+f"(c[1]), "+f"(c[2]), "+f"(c[3])
        : "r"(a[0]), "r"(a[1]), "r"(a[2]), "r"(a[3]), "r"(b[0]), "r"(b[1]));
}

// ---------------------------------------------------------------------------
// tf32 warp-MMA GEMM, 64x64 warp tiles, 3-stage cp.async pipeline.
//   C[b](MxN) = A[b](MxK, k-contig) * B[b]
//   BT=false (NN): B stored [K x N], n-contig; warp grid 2(m) x 4(n), CTA 128x256
//   BT=true  (NT): B stored [N x K], k-contig; warp grid 4(m) x 2(n), CTA 256x128
//   KA  : K % 32 == 0 and rows 16B-aligned (else 4B cp.async path for A)
//   EMUL: epilogue C[m,n] *= E[m*N + n]
//   ROUND: round epilogue output to tf32 (rna)
//   FRA : round A fragments (rna) at SMEM->register load
// 8 warps, 1 CTA/SM (high regs + ~155KB smem).
// ---------------------------------------------------------------------------
#define BK 32
#define NSTG 3

template <bool BT, bool KA, bool EMUL, bool ROUND, bool FRA>
__global__ void __launch_bounds__(256, 1)
mma_gemm(const float* __restrict__ A, const float* __restrict__ Bm,
         float* __restrict__ C, const float* __restrict__ E,
         int M, int N, int K,
         long long sA, long long sB, long long sC)
{
    constexpr int WM = BT ? 4 : 2;           // warp rows
    constexpr int WN = BT ? 2 : 4;           // warp cols
    constexpr int BM = WM * 64;              // 256 / 128
    constexpr int BN = WN * 64;              // 128 / 256

    constexpr int A_BYTES = BM * 36 * 4;
    constexpr int BSTRIDE = BT ? 36 : (BN + 8);
    constexpr int B_ROWS  = BT ? BN : BK;
    constexpr int B_BYTES = B_ROWS * BSTRIDE * 4;

    extern __shared__ char smc[];
    const uint32_t smA = smem_u32(smc);
    const uint32_t smB = smA + NSTG * A_BYTES;

    const int bz = blockIdx.z;
    A  += (long long)bz * sA;
    Bm += (long long)bz * sB;
    C  += (long long)bz * sC;

    const int m0 = blockIdx.y * BM;
    const int n0 = blockIdx.x * BN;

    const int tid = threadIdx.x;
    const int wid = tid >> 5;
    const int lid = tid & 31;
    const int g   = lid >> 2;
    const int tig = lid & 3;
    const int mb  = (wid / WN) * 64;
    const int nb  = (wid % WN) * 64;

    const int nK = (K + BK - 1) / BK;

    // ---- async tile issue ----
    auto issueA = [&](int kt, int buf) {
        const uint32_t base = smA + buf * A_BYTES;
        if (KA) {
#pragma unroll
            for (int i = 0; i < BM / 32; i++) {
                const int slot = tid + i * 256;       // BM*8 16B slots
                const int row  = slot >> 3;
                const int c4   = slot & 7;
                int gm = m0 + row; if (gm > M - 1) gm = M - 1;  // clamp (junk rows masked at epi)
                cp16(base + row * 144 + c4 * 16,
                     A + (long long)gm * K + kt * BK + c4 * 4);
            }
        } else {
#pragma unroll
            for (int i = 0; i < BM / 8; i++) {
                const int slot = tid + i * 256;       // BM*32 scalar slots
                const int row  = slot >> 5;
                const int col  = slot & 31;
                const int gm   = m0 + row;
                const int gk   = kt * BK + col;
                const int sz   = (gk < K && gm < M) ? 4 : 0;
                const int cm   = gm < M ? gm : M - 1;
                const int ck   = gk < K ? gk : K - 1;
                cp4(base + row * 144 + col * 4, A + (long long)cm * K + ck, sz);
            }
        }
    };
    auto issueB = [&](int kt, int buf) {
        const uint32_t base = smB + buf * B_BYTES;
        if (BT) {
            // [n][k]; N is a multiple of BN for all NT stages -> no n guards
#pragma unroll
            for (int i = 0; i < BN / 32; i++) {
                const int slot = tid + i * 256;
                const int nrow = slot >> 3;
                const int c4   = slot & 7;
                cp16(base + nrow * 144 + c4 * 16,
                     Bm + (long long)(n0 + nrow) * K + kt * BK + c4 * 4);
            }
        } else {
            // [k][n]; zero-fill k tail
#pragma unroll
            for (int i = 0; i < BN / 32; i++) {
                const int slot = tid + i * 256;       // BK*BN/4 slots
                const int kr   = slot / (BN / 4);
                const int n4   = (slot % (BN / 4)) * 4;
                const int gk   = kt * BK + kr;
                const int sz   = (KA || gk < K) ? 16 : 0;
                const int ck   = gk < K ? gk : K - 1;
                cp16z(base + (kr * BSTRIDE + n4) * 4,
                      Bm + (long long)ck * N + n0 + n4, sz);
            }
        }
    };

    float acc[4][8][4];
#pragma unroll
    for (int mt = 0; mt < 4; mt++)
#pragma unroll
        for (int nt = 0; nt < 8; nt++)
#pragma unroll
            for (int r = 0; r < 4; r++) acc[mt][nt][r] = 0.0f;

    // ---- prologue: NSTG-1 stages in flight ----
#pragma unroll
    for (int s = 0; s < NSTG - 1; s++) {
        if (s < nK) { issueA(s, s); issueB(s, s); }
        cp_commit();
    }

    // ---- main loop ----
    for (int kt = 0; kt < nK; kt++) {
        cp_wait<NSTG - 2>();
        __syncthreads();

        const int nxt = kt + NSTG - 1;
        if (nxt < nK) { issueA(nxt, nxt % NSTG); issueB(nxt, nxt % NSTG); }
        cp_commit();

        const int buf = kt % NSTG;
        const float (*As)[36] =
            reinterpret_cast<const float(*)[36]>(smc + buf * A_BYTES);
        const float (*Bs)[BSTRIDE] =
            reinterpret_cast<const float(*)[BSTRIDE]>(smc + NSTG * A_BYTES + buf * B_BYTES);

#pragma unroll
        for (int ks = 0; ks < 4; ks++) {
            const int kb = ks * 8;
            uint32_t af[4][4];
#pragma unroll
            for (int mt = 0; mt < 4; mt++) {
                const int m = mb + mt * 16;
                float a0 = As[m + g    ][kb + tig    ];
                float a1 = As[m + g + 8][kb + tig    ];
                float a2 = As[m + g    ][kb + tig + 4];
                float a3 = As[m + g + 8][kb + tig + 4];
                if (FRA) { a0 = tf32r(a0); a1 = tf32r(a1); a2 = tf32r(a2); a3 = tf32r(a3); }
                af[mt][0] = __float_as_uint(a0);
                af[mt][1] = __float_as_uint(a1);
                af[mt][2] = __float_as_uint(a2);
                af[mt][3] = __float_as_uint(a3);
            }
            uint32_t bf[8][2];
#pragma unroll
            for (int nt = 0; nt < 8; nt++) {
                const int n = nb + nt * 8 + g;
                if (BT) {
                    bf[nt][0] = __float_as_uint(Bs[n][kb + tig    ]);
                    bf[nt][1] = __float_as_uint(Bs[n][kb + tig + 4]);
                } else {
                    bf[nt][0] = __float_as_uint(Bs[kb + tig    ][n]);
                    bf[nt][1] = __float_as_uint(Bs[kb + tig + 4][n]);
                }
            }
#pragma unroll
            for (int mt = 0; mt < 4; mt++)
#pragma unroll
                for (int nt = 0; nt < 8; nt++)
                    mma_tf32(acc[mt][nt], af[mt], bf[nt]);
        }
    }

    // ---- epilogue ----
#pragma unroll
    for (int mt = 0; mt < 4; mt++) {
        const int r0 = m0 + mb + mt * 16 + g;
        const int r1 = r0 + 8;
#pragma unroll
        for (int nt = 0; nt < 8; nt++) {
            const int cb = n0 + nb + nt * 8 + 2 * tig;
            if (r0 < M) {
                float2 v = make_float2(acc[mt][nt][0], acc[mt][nt][1]);
                if (EMUL) {
                    const float* e = E + (long long)r0 * N + cb;
                    v.x *= e[0]; v.y *= e[1];
                }
                if (ROUND) { v.x = tf32r(v.x); v.y = tf32r(v.y); }
                *reinterpret_cast<float2*>(C + (long long)r0 * N + cb) = v;
            }
            if (r1 < M) {
                float2 v = make_float2(acc[mt][nt][2], acc[mt][nt][3]);
                if (EMUL) {
                    const float* e = E + (long long)r1 * N + cb;
                    v.x *= e[0]; v.y *= e[1];
                }
                if (ROUND) { v.x = tf32r(v.x); v.y = tf32r(v.y); }
                *reinterpret_cast<float2*>(C + (long long)r1 * N + cb) = v;
            }
        }
    }
}

// ---------------------------------------------------------------------------
// Two-pass online row softmax (in place); R: tf32-round the normalized output.
// ---------------------------------------------------------------------------
template <bool R>
__global__ void __launch_bounds__(256)
softmax_rows(float* __restrict__ X, int rowlen)
{
    const long long row = blockIdx.x;
    float* x = X + row * (long long)rowlen;
    float4* x4 = reinterpret_cast<float4*>(x);
    const int n4 = rowlen >> 2;
    const int tid = threadIdx.x;
    const int T = blockDim.x;
    __shared__ float sm_m[8], sm_s[8];

    float m = -CUDART_INF_F, s = 0.0f;
    for (int i = tid; i < n4; i += T) {
        float4 v = x4[i];
        float m4 = fmaxf(fmaxf(v.x, v.y), fmaxf(v.z, v.w));
        if (m4 > m) { s *= __expf(m - m4); m = m4; }
        s += __expf(v.x - m) + __expf(v.y - m) + __expf(v.z - m) + __expf(v.w - m);
    }
#pragma unroll
    for (int o = 16; o; o >>= 1) {
        float om = __shfl_xor_sync(0xffffffffu, m, o);
        float os = __shfl_xor_sync(0xffffffffu, s, o);
        float nm = fmaxf(m, om);
        s = s * __expf(m - nm) + os * __expf(om - nm);
        m = nm;
    }
    if ((tid & 31) == 0) { sm_m[tid >> 5] = m; sm_s[tid >> 5] = s; }
    __syncthreads();
    if (tid < 32) {
        const int nw = T >> 5;
        float mm = (tid < nw) ? sm_m[tid] : -CUDART_INF_F;
        float ss = (tid < nw) ? sm_s[tid] : 0.0f;
#pragma unroll
        for (int o = 4; o; o >>= 1) {
            float om = __shfl_xor_sync(0xffffffffu, mm, o);
            float os = __shfl_xor_sync(0xffffffffu, ss, o);
            float nm = fmaxf(mm, om);
            ss = ss * __expf(mm - nm) + os * __expf(om - nm);
            mm = nm;
        }
        if (tid == 0) { sm_m[0] = mm; sm_s[0] = ss; }
    }
    __syncthreads();
    m = sm_m[0];
    const float inv = 1.0f / sm_s[0];

    for (int i = tid; i < n4; i += T) {
        float4 v = x4[i];
        v.x = __expf(v.x - m) * inv; v.y = __expf(v.y - m) * inv;
        v.z = __expf(v.z - m) * inv; v.w = __expf(v.w - m) * inv;
        if (R) { v.x = tf32r(v.x); v.y = tf32r(v.y); v.z = tf32r(v.z); v.w = tf32r(v.w); }
        x4[i] = v;
    }
}

// ---------------------------------------------------------------------------
// Prep: tf32 rna rounding of raw inputs
// ---------------------------------------------------------------------------
__global__ void round_copy(const float* __restrict__ x, float* __restrict__ y, long long n)
{
    long long i = ((long long)blockIdx.x * blockDim.x + threadIdx.x) * 4;
    if (i + 3 < n) {
        float4 v = *reinterpret_cast<const float4*>(x + i);
        v.x = tf32r(v.x); v.y = tf32r(v.y); v.z = tf32r(v.z); v.w = tf32r(v.w);
        *reinterpret_cast<float4*>(y + i) = v;
    } else {
        for (long long j = i; j < n; j++) y[j] = tf32r(x[j]);
    }
}

// ---------------------------------------------------------------------------
// Pipeline (graph-capturable: kernel launches only)
// ---------------------------------------------------------------------------
extern "C" void kernel_launch(void* const* d_in, const int* in_sizes, int n_in,
                              void* d_out, int out_size)
{
    const float* H   = (const float*)d_in[0];   // [B, D, L]
    const float* Q1w = (const float*)d_in[1];   // [N1, D]
    const float* Q2w = (const float*)d_in[2];   // [N2, D]
    const float* Q12 = (const float*)d_in[3];   // [N2, N1]

    float* C2 = (float*)d_out;                                // [B, N2, D]
    float* A2 = (float*)d_out + (long long)B_ * N2_ * D_;     // [B, N2, L]

    float *pE1, *pC1, *pQ2, *pHr, *pQ1r, *pQ12r;
    cudaGetSymbolAddress((void**)&pE1,  g_E1);
    cudaGetSymbolAddress((void**)&pC1,  g_C1);
    cudaGetSymbolAddress((void**)&pQ2,  g_Q2);
    cudaGetSymbolAddress((void**)&pHr,  g_Hr);
    cudaGetSymbolAddress((void**)&pQ1r, g_Q1r);
    cudaGetSymbolAddress((void**)&pQ12r, g_Q12r);

    // NN: A 128x36, B 32x264 per stage; NT: A 256x36, B 128x36 per stage
    constexpr int SM_NN = NSTG * (128 * 36 * 4) + NSTG * (32 * 264 * 4);  // 156672
    constexpr int SM_NT = NSTG * (256 * 36 * 4) + NSTG * (128 * 36 * 4);  // 165888

    cudaFuncSetAttribute(mma_gemm<false, true,  false, false, false>,
                         cudaFuncAttributeMaxDynamicSharedMemorySize, SM_NN);
    cudaFuncSetAttribute(mma_gemm<true,  true,  false, true,  false>,
                         cudaFuncAttributeMaxDynamicSharedMemorySize, SM_NT);
    cudaFuncSetAttribute(mma_gemm<false, false, true,  true,  false>,
                         cudaFuncAttributeMaxDynamicSharedMemorySize, SM_NN);
    cudaFuncSetAttribute(mma_gemm<true,  true,  false, false, true >,
                         cudaFuncAttributeMaxDynamicSharedMemorySize, SM_NT);

    const long long sH  = (long long)D_ * L_;
    const long long sE1 = (long long)N1_ * L_;
    const long long sC1 = (long long)N1_ * D_;
    const long long sQ2 = (long long)N2_ * D_;
    const long long sA2 = (long long)N2_ * L_;
    const long long sC2 = (long long)N2_ * D_;

    // prep: tf32-round H, Q1_w, Q12_w
    {
        long long nh = (long long)B_ * D_ * L_;
        round_copy<<<(unsigned)((nh / 4 + 255) / 256), 256>>>(H, pHr, nh);
        long long n1 = (long long)N1_ * D_;
        round_copy<<<(unsigned)((n1 / 4 + 255) / 256), 256>>>(Q1w, pQ1r, n1);
        long long n12 = (long long)N2_ * N1_;
        round_copy<<<(unsigned)((n12 / 4 + 255) / 256), 256>>>(Q12, pQ12r, n12);
    }

    // 1) E1 = Q1r . Hr          NN (CTA 128x256): x=4096/256, y=ceil(1167/128)
    mma_gemm<false, true, false, false, false>
        <<<dim3(L_ / 256, (N1_ + 127) / 128, B_), 256, SM_NN>>>(
        pQ1r, pHr, pE1, nullptr, N1_, L_, D_, 0, sH, sE1);

    // 2) A1 = softmax(E1), tf32-rounded
    softmax_rows<true><<<B_ * N1_, 256>>>(pE1, L_);

    // 3) C1 = A1 . Hr^T         NT (CTA 256x128): x=512/128, y=ceil(1167/256)
    mma_gemm<true, true, false, true, false>
        <<<dim3(D_ / 128, (N1_ + 255) / 256, B_), 256, SM_NT>>>(
        pE1, pHr, pC1, nullptr, N1_, D_, L_, sE1, sH, sC1);

    // 4) Q2 = (Q12r . C1) * Q2w NN, K=1167 (4B async A path)
    mma_gemm<false, false, true, true, false>
        <<<dim3(D_ / 256, (N2_ + 127) / 128, B_), 256, SM_NN>>>(
        pQ12r, pC1, pQ2, Q2w, N2_, D_, N1_, 0, sC1, sQ2);

    // 5) E2 = Q2 . Hr           NN -> A2 region
    mma_gemm<false, true, false, false, false>
        <<<dim3(L_ / 256, (N2_ + 127) / 128, B_), 256, SM_NN>>>(
        pQ2, pHr, A2, nullptr, N2_, L_, D_, sQ2, sH, sA2);

    // 6) A2 = softmax(E2), fp32 (output)
    softmax_rows<false><<<B_ * N2_, 256>>>(A2, L_);

    // 7) C2 = A2 . Hr^T         NT, A fragments tf32-rounded on load
    mma_gemm<true, true, false, false, true>
        <<<dim3(D_ / 128, (N2_ + 255) / 256, B_), 256, SM_NT>>>(
        A2, pHr, C2, nullptr, N2_, D_, L_, sA2, sH, sC2);
}

// round 6
// speedup vs baseline: 4.8846x; 1.2195x over previous
#include <cuda_runtime.h>
#include <cstdint>
#include <math_constants.h>

// Problem constants (fixed by the dataset)
static constexpr int B_  = 4;
static constexpr int D_  = 512;
static constexpr int L_  = 4096;
static constexpr int N1_ = 1167;
static constexpr int N2_ = 8921;
static constexpr int N1P = 1184;             // N1 padded to 32 (16B-aligned rows)

// ---------------------------------------------------------------------------
// Scratch (__device__ globals; no cudaMalloc allowed)
// ---------------------------------------------------------------------------
__device__ float g_E1 [(size_t)B_ * N1_ * L_];   // E1 / A1   [B, N1, L]
__device__ float g_C1t[(size_t)B_ * D_  * N1P];  // C1^T pad  [B, D, N1P]
__device__ float g_Q2 [(size_t)B_ * N2_ * D_];   // mod. Q2   [B, N2, D]
__device__ float g_Hr [(size_t)B_ * D_ * L_];    // tf32-rounded H      [B, D, L]
__device__ float g_Ht [(size_t)B_ * L_ * D_];    // tf32-rounded H^T    [B, L, D]
__device__ float g_Q1r[(size_t)N1_ * D_];        // tf32-rounded Q1_w
__device__ float g_Q12p[(size_t)N2_ * N1P];      // tf32-rounded, padded Q12_w

// ---------------------------------------------------------------------------
// Helpers
// ---------------------------------------------------------------------------
__device__ __forceinline__ float tf32r(float x) {
    uint32_t o;
    asm("cvt.rna.tf32.f32 %0, %1;" : "=r"(o) : "f"(x));
    return __uint_as_float(o);
}
__device__ __forceinline__ uint32_t tf32ru(uint32_t x) {
    uint32_t o;
    asm("cvt.rna.tf32.f32 %0, %1;" : "=r"(o) : "f"(__uint_as_float(x)));
    return o;
}
__device__ __forceinline__ uint32_t smem_u32(const void* p) {
    uint32_t a;
    asm("{ .reg .u64 t; cvta.to.shared.u64 t, %1; cvt.u32.u64 %0, t; }"
        : "=r"(a) : "l"(p));
    return a;
}
__device__ __forceinline__ void cp16(uint32_t dst, const float* src) {
    asm volatile("cp.async.cg.shared.global [%0], [%1], 16;"
                 :: "r"(dst), "l"(src));
}
__device__ __forceinline__ void cp_commit() {
    asm volatile("cp.async.commit_group;" ::: "memory");
}
template <int N>
__device__ __forceinline__ void cp_wait() {
    asm volatile("cp.async.wait_group %0;" :: "n"(N) : "memory");
}
__device__ __forceinline__ void ldsm4(uint32_t& r0, uint32_t& r1,
                                      uint32_t& r2, uint32_t& r3, uint32_t addr) {
    asm volatile("ldmatrix.sync.aligned.m8n8.x4.shared.b16 {%0,%1,%2,%3}, [%4];"
                 : "=r"(r0), "=r"(r1), "=r"(r2), "=r"(r3) : "r"(addr));
}
__device__ __forceinline__ void mma_tf32(float* c, const uint32_t* a, const uint32_t* b) {
    asm volatile(
        "mma.sync.aligned.m16n8k8.row.col.f32.tf32.tf32.f32 "
        "{%0,%1,%2,%3}, {%4,%5,%6,%7}, {%8,%9}, {%0,%1,%2,%3};"
        : "+f"(c[0]), "+f"(c[1]), "+f"(c[2]), "+f"(c[3])
        : "r"(a[0]), "r"(a[1]), "r"(a[2]), "r"(a[3]), "r"(b[0]), "r"(b[1]));
}

// ---------------------------------------------------------------------------
// All-NT tf32 warp-MMA GEMM with ldmatrix fragments + cp.async pipeline.
//   C[b](MxN) = A[b](MxK, k-contig) * B[b]^T   (B stored [N x K], k-contig)
//   K % 32 == 0, all rows 16B-aligned (callers guarantee via padding).
//   EMUL : epilogue C[m,n] *= E[m*N + n] (unbatched)
//   ROUND: round epilogue output to tf32 (rna)
//   FRA  : round A fragments at ldsm time (for unrounded A operand)
//   TROUT: store transposed C[n*ldC + m] (else C[m*ldC + n])
// CTA tile 128x128, 4 warps (2x2) of 64x64, BK=32, 3-stage, 2 CTAs/SM.
// SMEM rows: 128B (32 floats) with 16B-chunk XOR swizzle p = c ^ (row&7).
// ---------------------------------------------------------------------------
#define BK 32
#define NSTG 3
static constexpr int TILE_BYTES = 128 * 128;           // 16 KB per operand stage
static constexpr int SMEM_TOT   = NSTG * 2 * TILE_BYTES; // 98304

template <bool EMUL, bool ROUND, bool FRA, bool TROUT>
__global__ void __launch_bounds__(128, 2)
mma_gemm(const float* __restrict__ A, const float* __restrict__ Bm,
         float* __restrict__ C, const float* __restrict__ E,
         int M, int N, int K, int ldC,
         long long sA, long long sB, long long sC)
{
    extern __shared__ char smc[];
    const uint32_t smA = smem_u32(smc);
    const uint32_t smB = smA + NSTG * TILE_BYTES;

    const int bz = blockIdx.z;
    A  += (long long)bz * sA;
    Bm += (long long)bz * sB;
    C  += (long long)bz * sC;

    const int m0 = blockIdx.y * 128;
    const int n0 = blockIdx.x * 128;

    const int tid = threadIdx.x;
    const int wid = tid >> 5;
    const int lid = tid & 31;
    const int g   = lid >> 2;
    const int tig = lid & 3;
    const int mb  = (wid >> 1) * 64;
    const int nb  = (wid & 1) * 64;

    const int nK = K / BK;

    // ---- async tile fills (XOR-swizzled 16B chunks, coalesced gmem) ----
    auto issueA = [&](int kt, int buf) {
        const uint32_t base = smA + buf * TILE_BYTES;
        const float* src = A + (long long)kt * BK;
#pragma unroll
        for (int i = 0; i < 8; i++) {
            const int s   = tid + i * 128;
            const int row = s >> 3;
            const int p   = s & 7;
            const int c   = p ^ (row & 7);
            int gm = m0 + row; if (gm > M - 1) gm = M - 1;   // clamp; junk masked at epi
            cp16(base + row * 128 + p * 16, src + (long long)gm * K + c * 4);
        }
    };
    auto issueB = [&](int kt, int buf) {
        const uint32_t base = smB + buf * TILE_BYTES;
        const float* src = Bm + (long long)kt * BK;
#pragma unroll
        for (int i = 0; i < 8; i++) {
            const int s   = tid + i * 128;
            const int row = s >> 3;
            const int p   = s & 7;
            const int c   = p ^ (row & 7);
            cp16(base + row * 128 + p * 16,
                 src + (long long)(n0 + row) * K + c * 4);   // N multiple of 128
        }
    };

    float acc[4][8][4];
#pragma unroll
    for (int mt = 0; mt < 4; mt++)
#pragma unroll
        for (int nt = 0; nt < 8; nt++)
#pragma unroll
            for (int r = 0; r < 4; r++) acc[mt][nt][r] = 0.0f;

    // per-lane fragment address components
    const uint32_t aOff  = (uint32_t)(mb + (lid & 15)) * 128;
    const int      aKsel = lid >> 4;                       // k-half select
    const uint32_t bOff  = (uint32_t)(nb + ((lid >> 4) << 3) + (lid & 7)) * 128;
    const int      bKsel = (lid >> 3) & 1;
    const uint32_t swz   = (uint32_t)(lid & 7) * 16;       // XOR in byte units

    // ---- prologue ----
#pragma unroll
    for (int s = 0; s < NSTG - 1; s++) {
        if (s < nK) { issueA(s, s); issueB(s, s); }
        cp_commit();
    }

    // ---- main loop ----
    for (int kt = 0; kt < nK; kt++) {
        cp_wait<NSTG - 2>();
        __syncthreads();

        const int nxt = kt + NSTG - 1;
        if (nxt < nK) { issueA(nxt, nxt % NSTG); issueB(nxt, nxt % NSTG); }
        cp_commit();

        const int buf = kt % NSTG;
        const uint32_t aBase = smA + buf * TILE_BYTES + aOff;
        const uint32_t bBase = smB + buf * TILE_BYTES + bOff;

#pragma unroll
        for (int ks = 0; ks < 4; ks++) {
            uint32_t af[4][4];
#pragma unroll
            for (int mt = 0; mt < 4; mt++) {
                const uint32_t addr =
                    aBase + mt * 2048 + ((((uint32_t)(ks * 2 + aKsel)) * 16) ^ swz);
                ldsm4(af[mt][0], af[mt][1], af[mt][2], af[mt][3], addr);
                if (FRA) {
                    af[mt][0] = tf32ru(af[mt][0]); af[mt][1] = tf32ru(af[mt][1]);
                    af[mt][2] = tf32ru(af[mt][2]); af[mt][3] = tf32ru(af[mt][3]);
                }
            }
            uint32_t bf[8][2];
#pragma unroll
            for (int j = 0; j < 4; j++) {
                const uint32_t addr =
                    bBase + j * 2048 + ((((uint32_t)(ks * 2 + bKsel)) * 16) ^ swz);
                ldsm4(bf[2 * j][0], bf[2 * j][1], bf[2 * j + 1][0], bf[2 * j + 1][1], addr);
            }
#pragma unroll
            for (int mt = 0; mt < 4; mt++)
#pragma unroll
                for (int nt = 0; nt < 8; nt++)
                    mma_tf32(acc[mt][nt], af[mt], bf[nt]);
        }
    }

    // ---- epilogue ----
#pragma unroll
    for (int mt = 0; mt < 4; mt++) {
        const int r0 = m0 + mb + mt * 16 + g;
        const int r1 = r0 + 8;
#pragma unroll
        for (int nt = 0; nt < 8; nt++) {
            const int cb = n0 + nb + nt * 8 + 2 * tig;
            if (TROUT) {
                if (r0 < M) {
                    float v0 = acc[mt][nt][0], v1 = acc[mt][nt][1];
                    if (ROUND) { v0 = tf32r(v0); v1 = tf32r(v1); }
                    C[(long long)(cb + 0) * ldC + r0] = v0;
                    C[(long long)(cb + 1) * ldC + r0] = v1;
                }
                if (r1 < M) {
                    float v2 = acc[mt][nt][2], v3 = acc[mt][nt][3];
                    if (ROUND) { v2 = tf32r(v2); v3 = tf32r(v3); }
                    C[(long long)(cb + 0) * ldC + r1] = v2;
                    C[(long long)(cb + 1) * ldC + r1] = v3;
                }
            } else {
                if (r0 < M) {
                    float2 v = make_float2(acc[mt][nt][0], acc[mt][nt][1]);
                    if (EMUL) {
                        const float* e = E + (long long)r0 * N + cb;
                        v.x *= e[0]; v.y *= e[1];
                    }
                    if (ROUND) { v.x = tf32r(v.x); v.y = tf32r(v.y); }
                    *reinterpret_cast<float2*>(C + (long long)r0 * ldC + cb) = v;
                }
                if (r1 < M) {
                    float2 v = make_float2(acc[mt][nt][2], acc[mt][nt][3]);
                    if (EMUL) {
                        const float* e = E + (long long)r1 * N + cb;
                        v.x *= e[0]; v.y *= e[1];
                    }
                    if (ROUND) { v.x = tf32r(v.x); v.y = tf32r(v.y); }
                    *reinterpret_cast<float2*>(C + (long long)r1 * ldC + cb) = v;
                }
            }
        }
    }
}

// ---------------------------------------------------------------------------
// Two-pass online row softmax (in place); R: tf32-round the normalized output.
// ---------------------------------------------------------------------------
template <bool R>
__global__ void __launch_bounds__(256)
softmax_rows(float* __restrict__ X, int rowlen)
{
    const long long row = blockIdx.x;
    float* x = X + row * (long long)rowlen;
    float4* x4 = reinterpret_cast<float4*>(x);
    const int n4 = rowlen >> 2;
    const int tid = threadIdx.x;
    const int T = blockDim.x;
    __shared__ float sm_m[8], sm_s[8];

    float m = -CUDART_INF_F, s = 0.0f;
    for (int i = tid; i < n4; i += T) {
        float4 v = x4[i];
        float m4 = fmaxf(fmaxf(v.x, v.y), fmaxf(v.z, v.w));
        if (m4 > m) { s *= __expf(m - m4); m = m4; }
        s += __expf(v.x - m) + __expf(v.y - m) + __expf(v.z - m) + __expf(v.w - m);
    }
#pragma unroll
    for (int o = 16; o; o >>= 1) {
        float om = __shfl_xor_sync(0xffffffffu, m, o);
        float os = __shfl_xor_sync(0xffffffffu, s, o);
        float nm = fmaxf(m, om);
        s = s * __expf(m - nm) + os * __expf(om - nm);
        m = nm;
    }
    if ((tid & 31) == 0) { sm_m[tid >> 5] = m; sm_s[tid >> 5] = s; }
    __syncthreads();
    if (tid < 32) {
        const int nw = T >> 5;
        float mm = (tid < nw) ? sm_m[tid] : -CUDART_INF_F;
        float ss = (tid < nw) ? sm_s[tid] : 0.0f;
#pragma unroll
        for (int o = 4; o; o >>= 1) {
            float om = __shfl_xor_sync(0xffffffffu, mm, o);
            float os = __shfl_xor_sync(0xffffffffu, ss, o);
            float nm = fmaxf(mm, om);
            ss = ss * __expf(mm - nm) + os * __expf(om - nm);
            mm = nm;
        }
        if (tid == 0) { sm_m[0] = mm; sm_s[0] = ss; }
    }
    __syncthreads();
    m = sm_m[0];
    const float inv = 1.0f / sm_s[0];

    for (int i = tid; i < n4; i += T) {
        float4 v = x4[i];
        v.x = __expf(v.x - m) * inv; v.y = __expf(v.y - m) * inv;
        v.z = __expf(v.z - m) * inv; v.w = __expf(v.w - m) * inv;
        if (R) { v.x = tf32r(v.x); v.y = tf32r(v.y); v.z = tf32r(v.z); v.w = tf32r(v.w); }
        x4[i] = v;
    }
}

// ---------------------------------------------------------------------------
// Prep kernels
// ---------------------------------------------------------------------------
__global__ void round_copy(const float* __restrict__ x, float* __restrict__ y, long long n)
{
    long long i = ((long long)blockIdx.x * blockDim.x + threadIdx.x) * 4;
    if (i + 3 < n) {
        float4 v = *reinterpret_cast<const float4*>(x + i);
        v.x = tf32r(v.x); v.y = tf32r(v.y); v.z = tf32r(v.z); v.w = tf32r(v.w);
        *reinterpret_cast<float4*>(y + i) = v;
    } else {
        for (long long j = i; j < n; j++) y[j] = tf32r(x[j]);
    }
}

// Q12 [N2, N1] -> tf32-rounded, zero-padded [N2, N1P]
__global__ void pad_round_q12(const float* __restrict__ x, float* __restrict__ y)
{
    long long i = (long long)blockIdx.x * blockDim.x + threadIdx.x;
    if (i >= (long long)N2_ * N1P) return;
    const int m = (int)(i / N1P);
    const int n = (int)(i % N1P);
    y[i] = (n < N1_) ? tf32r(x[(long long)m * N1_ + n]) : 0.0f;
}

// H [B, D, L] -> Hr (rounded, same layout) + Ht (rounded, [B, L, D])
__global__ void prep_H(const float* __restrict__ H, float* __restrict__ Hr,
                       float* __restrict__ Ht)
{
    __shared__ float t[32][33];
    const int b  = blockIdx.z;
    const int l0 = blockIdx.x * 32;
    const int d0 = blockIdx.y * 32;
    const int lx = threadIdx.x, ly = threadIdx.y; // block (32, 8)
    const long long hb = (long long)b * D_ * L_;
#pragma unroll
    for (int i = 0; i < 32; i += 8) {
        const int d = d0 + ly + i, l = l0 + lx;
        float v = tf32r(H[hb + (long long)d * L_ + l]);
        Hr[hb + (long long)d * L_ + l] = v;
        t[ly + i][lx] = v;
    }
    __syncthreads();
    const long long tb = (long long)b * L_ * D_;
#pragma unroll
    for (int i = 0; i < 32; i += 8) {
        const int l = l0 + ly + i, d = d0 + lx;
        Ht[tb + (long long)l * D_ + d] = t[lx][ly + i];
    }
}

// zero the padded K-tail of C1t: [b][d][1167..1184)
__global__ void zero_c1t_tail(float* __restrict__ C1t)
{
    const int i = blockIdx.x * blockDim.x + threadIdx.x;
    const int total = B_ * D_ * (N1P - N1_);
    if (i >= total) return;
    const int bd = i / (N1P - N1_);
    const int j  = i % (N1P - N1_);
    C1t[(long long)bd * N1P + N1_ + j] = 0.0f;
}

// ---------------------------------------------------------------------------
// Pipeline (graph-capturable: kernel launches only)
// ---------------------------------------------------------------------------
extern "C" void kernel_launch(void* const* d_in, const int* in_sizes, int n_in,
                              void* d_out, int out_size)
{
    const float* H   = (const float*)d_in[0];   // [B, D, L]
    const float* Q1w = (const float*)d_in[1];   // [N1, D]
    const float* Q2w = (const float*)d_in[2];   // [N2, D]
    const float* Q12 = (const float*)d_in[3];   // [N2, N1]

    float* C2 = (float*)d_out;                                // [B, N2, D]
    float* A2 = (float*)d_out + (long long)B_ * N2_ * D_;     // [B, N2, L]

    float *pE1, *pC1t, *pQ2, *pHr, *pHt, *pQ1r, *pQ12p;
    cudaGetSymbolAddress((void**)&pE1,   g_E1);
    cudaGetSymbolAddress((void**)&pC1t,  g_C1t);
    cudaGetSymbolAddress((void**)&pQ2,   g_Q2);
    cudaGetSymbolAddress((void**)&pHr,   g_Hr);
    cudaGetSymbolAddress((void**)&pHt,   g_Ht);
    cudaGetSymbolAddress((void**)&pQ1r,  g_Q1r);
    cudaGetSymbolAddress((void**)&pQ12p, g_Q12p);

    cudaFuncSetAttribute(mma_gemm<false, false, false, false>,
                         cudaFuncAttributeMaxDynamicSharedMemorySize, SMEM_TOT);
    cudaFuncSetAttribute(mma_gemm<false, true,  false, true >,
                         cudaFuncAttributeMaxDynamicSharedMemorySize, SMEM_TOT);
    cudaFuncSetAttribute(mma_gemm<true,  true,  false, false>,
                         cudaFuncAttributeMaxDynamicSharedMemorySize, SMEM_TOT);
    cudaFuncSetAttribute(mma_gemm<false, false, true,  false>,
                         cudaFuncAttributeMaxDynamicSharedMemorySize, SMEM_TOT);

    const long long sH   = (long long)D_ * L_;
    const long long sHt  = (long long)L_ * D_;
    const long long sE1  = (long long)N1_ * L_;
    const long long sC1t = (long long)D_ * N1P;
    const long long sQ2  = (long long)N2_ * D_;
    const long long sA2  = (long long)N2_ * L_;
    const long long sC2  = (long long)N2_ * D_;

    // ---- prep ----
    {
        long long n1 = (long long)N1_ * D_;
        round_copy<<<(unsigned)((n1 / 4 + 255) / 256), 256>>>(Q1w, pQ1r, n1);
        long long n12p = (long long)N2_ * N1P;
        pad_round_q12<<<(unsigned)((n12p + 255) / 256), 256>>>(Q12, pQ12p);
        prep_H<<<dim3(L_ / 32, D_ / 32, B_), dim3(32, 8)>>>(H, pHr, pHt);
        zero_c1t_tail<<<(B_ * D_ * (N1P - N1_) + 255) / 256, 256>>>(pC1t);
    }

    const int gy1 = (N1_ + 127) / 128;   // 10
    const int gy2 = (N2_ + 127) / 128;   // 70

    // 1) E1[b,n,l] = Q1r[n,:] . Ht[b,l,:]           NT, K=512
    mma_gemm<false, false, false, false>
        <<<dim3(L_ / 128, gy1, B_), 128, SMEM_TOT>>>(
        pQ1r, pHt, pE1, nullptr, N1_, L_, D_, L_, 0, sHt, sE1);

    // 2) A1 = softmax(E1), tf32-rounded
    softmax_rows<true><<<B_ * N1_, 256>>>(pE1, L_);

    // 3) C1t[b,d,n] = A1[b,n,:] . Hr[b,d,:]         NT, K=4096, transposed+rounded out
    mma_gemm<false, true, false, true>
        <<<dim3(D_ / 128, gy1, B_), 128, SMEM_TOT>>>(
        pE1, pHr, pC1t, nullptr, N1_, D_, L_, N1P, sE1, sH, sC1t);

    // 4) Q2[b,m,d] = (Q12p[m,:] . C1t[b,d,:]) * Q2w[m,d]   NT, K=1184, rounded
    mma_gemm<true, true, false, false>
        <<<dim3(D_ / 128, gy2, B_), 128, SMEM_TOT>>>(
        pQ12p, pC1t, pQ2, Q2w, N2_, D_, N1P, D_, 0, sC1t, sQ2);

    // 5) E2[b,m,l] = Q2[b,m,:] . Ht[b,l,:]          NT, K=512 -> A2 region
    mma_gemm<false, false, false, false>
        <<<dim3(L_ / 128, gy2, B_), 128, SMEM_TOT>>>(
        pQ2, pHt, A2, nullptr, N2_, L_, D_, L_, sQ2, sHt, sA2);

    // 6) A2 = softmax(E2), fp32 (graded output)
    softmax_rows<false><<<B_ * N2_, 256>>>(A2, L_);

    // 7) C2[b,m,d] = A2[b,m,:] . Hr[b,d,:]          NT, K=4096, A rounded at ldsm
    mma_gemm<false, false, true, false>
        <<<dim3(D_ / 128, gy2, B_), 128, SMEM_TOT>>>(
        A2, pHr, C2, nullptr, N2_, D_, L_, D_, sA2, sH, sC2);
}